// round 15
// baseline (speedup 1.0000x reference)
#include <cuda_runtime.h>
#include <cuda_fp16.h>
#include <mma.h>
#include <math.h>
#include <stdint.h>

using namespace nvcuda;

#define BB 256
#define PP 620
#define CC 512
#define TT 32
#define VV 140
#define HH 256
#define AA 256
#define KIH (VV + AA)         // 396
#define KTOT (VV + AA + HH)   // 652 : [x | ctx | h]
#define NG   (4 * HH)         // 1024 gates
#define NS   4                // attention cp.async ring depth (pair-stages)
#define SPK  8                // gates split-K factor
#define GRID 148              // persistent CTAs (<= SM count, co-resident)

// proj tiling (v4): 64M x 128N tile, 32-k stages, padded ldm
#define PK   32
#define PLDM2 36              // 36 mod 32 == 4 -> same conflict-free pattern as 20

// ---------------- scratch (device globals; no allocations allowed) ----------
__device__ __half g_attn[(size_t)BB * PP * AA];   // 81.3 MB (fp16)
__device__ float  g_inp[BB * KTOT];               // packed [x | ctx | h]
__device__ float  g_c[BB * HH];
__device__ float  g_q[BB * AA];
__device__ float  g_gpart[SPK][BB * NG];          // split-K partials
__device__ unsigned g_tix[TT * 4];                // grid-barrier tickets (monotonic)
__device__ unsigned g_qdone;                      // q completion flag (reset each step)

// ---------------- helpers ----------------
__device__ __forceinline__ float warp_sum(float v) {
#pragma unroll
    for (int o = 16; o > 0; o >>= 1) v += __shfl_xor_sync(0xFFFFFFFFu, v, o);
    return v;
}
__device__ __forceinline__ float sigmoidf_(float x) { return 1.0f / (1.0f + __expf(-x)); }
__device__ __forceinline__ unsigned smem_u32(const void* p) {
    return (unsigned)__cvta_generic_to_shared(p);
}
__device__ __forceinline__ void load8h(float* v, const __half* p) {
    uint4 u = *(const uint4*)p;
    float2 f;
    f = __half22float2(*reinterpret_cast<__half2*>(&u.x)); v[0] = f.x; v[1] = f.y;
    f = __half22float2(*reinterpret_cast<__half2*>(&u.y)); v[2] = f.x; v[3] = f.y;
    f = __half22float2(*reinterpret_cast<__half2*>(&u.z)); v[4] = f.x; v[5] = f.y;
    f = __half22float2(*reinterpret_cast<__half2*>(&u.w)); v[6] = f.x; v[7] = f.y;
}

#define CP_ASYNC16(dst32, src) \
    asm volatile("cp.async.cg.shared.global [%0], [%1], 16;" :: "r"(dst32), "l"(src))
#define CP_COMMIT() asm volatile("cp.async.commit_group;")
#define CP_WAIT(N)  asm volatile("cp.async.wait_group %0;" :: "n"(N))
// named barrier over one 256-thread half (ids 1 and 2; 0 is __syncthreads)
#define NB(half) asm volatile("bar.sync %0, 256;" :: "r"((half) + 1) : "memory")

// Grid-wide barrier: monotonic ticket per slot — safe across graph replays.
__device__ __forceinline__ void grid_barrier(int slot) {
    __syncthreads();
    if (threadIdx.x == 0) {
        __threadfence();
        unsigned t = atomicAdd(&g_tix[slot], 1u);
        unsigned target = (t / GRID + 1u) * GRID;
        while (*((volatile unsigned*)&g_tix[slot]) < target) {}
    }
    __syncthreads();
}

// ============================================================================
// Kernel 1: projection  attn[m, a] = sum_c img[m, c] * Ic_w[a, c] + Ic_b[a]
// v4: 64M x 128N tiles, 32-k stages (16 stages total -> half the syncs of v3),
// ldm=36 padded smem, double-buffered cp.async, tf32 wmma.
// 8 warps in 2(m) x 4(n); warp tile 32x32 = 2x2 fragments.
// Dynamic smem 55296 B; epilogue patches overlay smA0.
// ============================================================================
__global__ __launch_bounds__(256, 3) void proj_kernel(const float* __restrict__ img,
                                                      const float* __restrict__ Icw,
                                                      const float* __restrict__ Icb) {
    extern __shared__ __align__(16) float psm[];
    float* const smA0 = psm;            // 64*36 = 2304 floats
    float* const smA1 = psm + 2304;
    float* const smB0 = psm + 4608;     // 128*36 = 4608 floats
    float* const smB1 = psm + 9216;     // total 13824 floats

    const int bm = blockIdx.x * 64;
    const int bn = blockIdx.y * 128;
    const int tid = threadIdx.x;
    const int warp = tid >> 5, lane = tid & 31;
    const int warp_m = warp & 1;   // 2 groups of 32 rows
    const int warp_n = warp >> 1;  // 4 groups of 32 cols
    const int NKS = CC / PK;       // 16 k-stages

    // per-stage loads: A 512 float4 (2/thread) + B 1024 float4 (4/thread)
    auto issue = [&](int ks, int buf) {
        const int k0 = ks * PK;
        float* sA = buf ? smA1 : smA0;
        float* sB = buf ? smB1 : smB0;
#pragma unroll
        for (int j = 0; j < 2; j++) {
            int idx = tid + j * 256;
            int row = idx >> 3, q = idx & 7;
            CP_ASYNC16(smem_u32(&sA[row * PLDM2 + q * 4]),
                       img + (size_t)(bm + row) * CC + k0 + q * 4);
        }
#pragma unroll
        for (int j = 0; j < 4; j++) {
            int idx = tid + j * 256;
            int row = idx >> 3, q = idx & 7;
            CP_ASYNC16(smem_u32(&sB[row * PLDM2 + q * 4]),
                       Icw + (size_t)(bn + row) * CC + k0 + q * 4);
        }
        CP_COMMIT();
    };

    wmma::fragment<wmma::accumulator, 16, 16, 8, float> acc[2][2];
#pragma unroll
    for (int mi = 0; mi < 2; mi++)
#pragma unroll
        for (int nj = 0; nj < 2; nj++) wmma::fill_fragment(acc[mi][nj], 0.0f);

    issue(0, 0);
    issue(1, 1);

    for (int ks = 0; ks < NKS; ks++) {
        if (ks + 1 < NKS) { CP_WAIT(1); } else { CP_WAIT(0); }
        __syncthreads();
        const int buf = ks & 1;
        const float* sA = buf ? smA1 : smA0;
        const float* sB = buf ? smB1 : smB0;
#pragma unroll
        for (int kk = 0; kk < PK; kk += 8) {
            wmma::fragment<wmma::matrix_a, 16, 16, 8, wmma::precision::tf32, wmma::row_major> fa[2];
            wmma::fragment<wmma::matrix_b, 16, 16, 8, wmma::precision::tf32, wmma::col_major> fb[2];
#pragma unroll
            for (int mi = 0; mi < 2; mi++)
                wmma::load_matrix_sync(fa[mi], &sA[(warp_m * 32 + mi * 16) * PLDM2 + kk], PLDM2);
#pragma unroll
            for (int nj = 0; nj < 2; nj++)
                wmma::load_matrix_sync(fb[nj], &sB[(warp_n * 32 + nj * 16) * PLDM2 + kk], PLDM2);
#pragma unroll
            for (int mi = 0; mi < 2; mi++)
#pragma unroll
                for (int nj = 0; nj < 2; nj++)
                    wmma::mma_sync(acc[mi][nj], fa[mi], fb[nj], acc[mi][nj]);
        }
        __syncthreads();
        if (ks + 2 < NKS) issue(ks + 2, buf);
    }

    // ---- epilogue: frag -> patch (overlays smA0) -> +bias -> fp16 ----
    __syncthreads();
    float* patch = psm + warp * 256;   // 8 warps * 256 = 2048 <= 2304
    const int prow = lane >> 1, pc0 = (lane & 1) * 8;
#pragma unroll
    for (int mi = 0; mi < 2; mi++) {
#pragma unroll
        for (int nj = 0; nj < 2; nj++) {
            wmma::store_matrix_sync(patch, acc[mi][nj], 16, wmma::mem_row_major);
            __syncwarp();
            const int gm = bm + warp_m * 32 + mi * 16 + prow;
            const int gc = bn + warp_n * 32 + nj * 16 + pc0;
            __half2 h2s[4];
#pragma unroll
            for (int j = 0; j < 4; j++) {
                float v0 = patch[prow * 16 + pc0 + 2 * j]     + Icb[gc + 2 * j];
                float v1 = patch[prow * 16 + pc0 + 2 * j + 1] + Icb[gc + 2 * j + 1];
                h2s[j] = __floats2half2_rn(v0, v1);
            }
            *(uint4*)&g_attn[(size_t)gm * AA + gc] = *(uint4*)h2s;
            __syncwarp();
        }
    }
}

// ============================================================================
// Kernel 2: init  g_inp = [x0 | 0 | 0], c = 0.
// ============================================================================
__global__ void init_kernel(const float* __restrict__ targets) {
    const int b = blockIdx.x;
    const int tid = threadIdx.x;
    for (int k = tid; k < KTOT; k += 256)
        g_inp[b * KTOT + k] = (k < VV) ? targets[(size_t)b * TT * VV + k] : 0.0f;
    g_c[b * HH + tid] = 0.0f;
}

// ============================================================================
// MEGAKERNEL phases.  148 CTAs x 512 threads, two independent 256-thread
// halves per CTA.  Cross-SM mutable data read via __ldcg (L1 not coherent
// inside one kernel).
// ============================================================================

// --- phase Q: q = h @ Hcw^T + Hcb.  32x32 tiles, 64 units (ctas 0..31).
// Ends with a release-flag increment (NO grid barrier after this phase:
// attention polls g_qdone == 64 instead). ---
__device__ __forceinline__ void q_phase(const float* __restrict__ Hcw,
                                        const float* __restrict__ Hcb,
                                        char* dynsm) {
    const int half = threadIdx.x >> 8;
    const int t2 = threadIdx.x & 255;
    const int u = blockIdx.x * 2 + half;
    if (u >= 64) return;
    float* sH = (float*)(dynsm + half * 20480);  // [64][33]
    float* sW = sH + 64 * 33;                    // [64][33]
    const int bm = (u >> 3) * 32;
    const int bn = (u & 7) * 32;
    const int a = t2 & 31;
    const int mg = t2 >> 5;

    float acc[4] = {0.f, 0.f, 0.f, 0.f};
    for (int k0 = 0; k0 < HH; k0 += 64) {
#pragma unroll
        for (int i = 0; i < 2; i++) {
            int qi = t2 + i * 256;
            int mm = qi >> 4, kq = qi & 15;
            float4 hv = __ldcg((const float4*)&g_inp[(bm + mm) * KTOT + KIH + k0 + kq * 4]);
            float4 wv = *(const float4*)&Hcw[(size_t)(bn + mm) * HH + k0 + kq * 4];
            sH[(kq * 4 + 0) * 33 + mm] = hv.x; sH[(kq * 4 + 1) * 33 + mm] = hv.y;
            sH[(kq * 4 + 2) * 33 + mm] = hv.z; sH[(kq * 4 + 3) * 33 + mm] = hv.w;
            sW[(kq * 4 + 0) * 33 + mm] = wv.x; sW[(kq * 4 + 1) * 33 + mm] = wv.y;
            sW[(kq * 4 + 2) * 33 + mm] = wv.z; sW[(kq * 4 + 3) * 33 + mm] = wv.w;
        }
        NB(half);
#pragma unroll
        for (int kk = 0; kk < 64; kk++) {
            float w = sW[kk * 33 + a];
#pragma unroll
            for (int r = 0; r < 4; r++)
                acc[r] = fmaf(sH[kk * 33 + mg * 4 + r], w, acc[r]);
        }
        NB(half);
    }
    float bias = Hcb[bn + a];
#pragma unroll
    for (int r = 0; r < 4; r++)
        g_q[(bm + mg * 4 + r) * AA + bn + a] = acc[r] + bias;

    // release: all threads fence their q stores, then one thread signals.
    __threadfence();
    NB(half);
    if (t2 == 0) atomicAdd(&g_qdone, 1u);
}

// --- phase A: attention.  ctas 0..127; half h handles b = cta*2 + h with
// 8 warps.  Prologue cp.asyncs are issued BEFORE waiting for q (overlap),
// then we spin on g_qdone == 64.  Warp wg owns rows p = wg + 8i. ---
__device__ __forceinline__ void attn_phase(char* dynsm, float* sm_m, float* sm_s) {
    const int cta = blockIdx.x;
    if (cta >= 128) return;
    const int tid = threadIdx.x;
    const int w = tid >> 5, l = tid & 31;
    const int half = w >> 3, wg = w & 7;
    const int b = cta * 2 + half;
    const __half* attb = g_attn + (size_t)b * PP * AA;
    __half* ring = (__half*)dynsm + w * (NS * 2 * AA);   // [NS][2][AA]

    const int nrow = (PP - wg + 7) >> 3;   // 78 (wg<4) or 77
    const int npair = 39;

#pragma unroll
    for (int it = 0; it < NS; it++) {
        CP_ASYNC16(smem_u32(ring + (it * 2 + 0) * AA + l * 8),
                   attb + (size_t)(wg + (2 * it) * 8) * AA + l * 8);
        CP_ASYNC16(smem_u32(ring + (it * 2 + 1) * AA + l * 8),
                   attb + (size_t)(wg + (2 * it + 1) * 8) * AA + l * 8);
        CP_COMMIT();
    }

    // wait for q producers (release-fenced atomic counter; reset each step)
    {
        volatile unsigned* f = &g_qdone;
        while (*f < 64u) {}
    }
    __threadfence();

    float q8[8];
    {
        float4 qa = __ldcg((const float4*)&g_q[b * AA + l * 8]);
        float4 qb = __ldcg((const float4*)&g_q[b * AA + l * 8 + 4]);
        q8[0] = qa.x; q8[1] = qa.y; q8[2] = qa.z; q8[3] = qa.w;
        q8[4] = qb.x; q8[5] = qb.y; q8[6] = qb.z; q8[7] = qb.w;
    }

    const float scale = 0.0625f;
    float m = -1e30f, ssum = 0.0f;
    float ctx[8] = {0.f, 0.f, 0.f, 0.f, 0.f, 0.f, 0.f, 0.f};

    for (int it = 0; it < npair; it++) {
        const int s = it & (NS - 1);
        CP_WAIT(NS - 1);

        float v0[8], v1[8];
        load8h(v0, ring + (s * 2 + 0) * AA + l * 8);
        load8h(v1, ring + (s * 2 + 1) * AA + l * 8);

        float d0 = 0.f, d1 = 0.f;
#pragma unroll
        for (int j = 0; j < 8; j++) { d0 = fmaf(q8[j], v0[j], d0); d1 = fmaf(q8[j], v1[j], d1); }
        d0 = warp_sum(d0);
        d1 = warp_sum(d1);

        const bool val1 = (2 * it + 1) < nrow;
        float sc0 = d0 * scale;
        float sc1 = val1 ? d1 * scale : -1e30f;
        float mn = fmaxf(m, fmaxf(sc0, sc1));
        float fac = __expf(m - mn);
        float e0 = __expf(sc0 - mn);
        float e1 = val1 ? __expf(sc1 - mn) : 0.0f;
        ssum = ssum * fac + e0 + e1;
        if (val1) {
#pragma unroll
            for (int j = 0; j < 8; j++)
                ctx[j] = fmaf(e1, v1[j], fmaf(e0, v0[j], ctx[j] * fac));
        } else {
#pragma unroll
            for (int j = 0; j < 8; j++)
                ctx[j] = fmaf(e0, v0[j], ctx[j] * fac);
        }
        m = mn;

        const int nit = it + NS;
        if (nit < npair) {
            const int i0 = 2 * nit, i1 = i0 + 1;
            CP_ASYNC16(smem_u32(ring + (s * 2 + 0) * AA + l * 8),
                       attb + (size_t)(wg + i0 * 8) * AA + l * 8);
            if (i1 < nrow)
                CP_ASYNC16(smem_u32(ring + (s * 2 + 1) * AA + l * 8),
                           attb + (size_t)(wg + i1 * 8) * AA + l * 8);
        }
        CP_COMMIT();
    }
    CP_WAIT(0);

    NB(half);   // all 8 warps of this half done with their rings
    float* cbuf = (float*)(dynsm + half * 32768);  // overlays this half's rings
    *(float4*)&cbuf[wg * AA + l * 8]     = make_float4(ctx[0], ctx[1], ctx[2], ctx[3]);
    *(float4*)&cbuf[wg * AA + l * 8 + 4] = make_float4(ctx[4], ctx[5], ctx[6], ctx[7]);
    if (l == 0) { sm_m[w] = m; sm_s[w] = ssum; }
    NB(half);

    const int t2 = tid & 255;  // column a
    float M = -1e30f;
#pragma unroll
    for (int ww = 0; ww < 8; ww++) M = fmaxf(M, sm_m[half * 8 + ww]);
    float S = 0.f, C = 0.f;
#pragma unroll
    for (int ww = 0; ww < 8; ww++) {
        float ef = __expf(sm_m[half * 8 + ww] - M);
        S += ef * sm_s[half * 8 + ww];
        C = fmaf(ef, cbuf[ww * AA + t2], C);
    }
    g_inp[b * KTOT + VV + t2] = C / S;
}

// --- phase G: gates GEMM.  64m x 128n tiles, 4x8 per-thread, splitK=8.
// 256 units = ctas 0..127 x 2 halves, one round. ---
__device__ __forceinline__ void gates_phase(const float* __restrict__ Wih,
                                            const float* __restrict__ Whh,
                                            char* dynsm) {
    const int half = threadIdx.x >> 8;
    const int t2 = threadIdx.x & 255;
    const int u = blockIdx.x * 2 + half;
    if (u >= 256) return;
    const int z  = u & 7;
    const int bn = ((u >> 3) & 7) * 128;
    const int bm = (u >> 6) * 64;

    float* sA = (float*)(dynsm + half * 16384);  // [16][68]
    float* sB = sA + 16 * 68;                    // [16][132]
    const int tm = t2 & 15, tn = t2 >> 4;
    const int arow = t2 >> 2, akq = t2 & 3;

    float acc[4][8] = {};
    float4 aR, bR0, bR1;

    auto loadP = [&](int k0) {
        const float4 z4 = make_float4(0.f, 0.f, 0.f, 0.f);
        int ka = k0 + akq * 4;
        aR = (ka + 3 < KTOT) ? __ldcg((const float4*)&g_inp[(bm + arow) * KTOT + ka]) : z4;
#pragma unroll
        for (int i = 0; i < 2; i++) {
            int idx = t2 + i * 256;
            int n = bn + (idx >> 2);
            int kb = k0 + (idx & 3) * 4;
            float4 v = z4;
            if (kb + 3 < KTOT) {
                if (kb + 3 < KIH) v = *(const float4*)&Wih[(size_t)n * KIH + kb];
                else              v = *(const float4*)&Whh[(size_t)n * HH + (kb - KIH)];
            }
            if (i == 0) bR0 = v; else bR1 = v;
        }
    };

    loadP(z * 16);

    for (int panel = z; panel * 16 < KTOT; panel += SPK) {
        sA[(akq * 4 + 0) * 68 + arow] = aR.x; sA[(akq * 4 + 1) * 68 + arow] = aR.y;
        sA[(akq * 4 + 2) * 68 + arow] = aR.z; sA[(akq * 4 + 3) * 68 + arow] = aR.w;
#pragma unroll
        for (int i = 0; i < 2; i++) {
            int idx = t2 + i * 256;
            int nl = idx >> 2, kq = idx & 3;
            float4 v = (i == 0) ? bR0 : bR1;
            sB[(kq * 4 + 0) * 132 + nl] = v.x; sB[(kq * 4 + 1) * 132 + nl] = v.y;
            sB[(kq * 4 + 2) * 132 + nl] = v.z; sB[(kq * 4 + 3) * 132 + nl] = v.w;
        }
        NB(half);

        if ((panel + SPK) * 16 < KTOT) loadP((panel + SPK) * 16);

#pragma unroll
        for (int kk = 0; kk < 16; kk++) {
            float4 a4  = *(const float4*)&sA[kk * 68 + tm * 4];
            float4 b4a = *(const float4*)&sB[kk * 132 + tn * 8];
            float4 b4b = *(const float4*)&sB[kk * 132 + tn * 8 + 4];
            const float ar[4] = {a4.x, a4.y, a4.z, a4.w};
            const float br[8] = {b4a.x, b4a.y, b4a.z, b4a.w, b4b.x, b4b.y, b4b.z, b4b.w};
#pragma unroll
            for (int r = 0; r < 4; r++)
#pragma unroll
                for (int c = 0; c < 8; c++)
                    acc[r][c] = fmaf(ar[r], br[c], acc[r][c]);
        }
        NB(half);
    }

    float* gp = g_gpart[z];
#pragma unroll
    for (int r = 0; r < 4; r++) {
        int row = bm + tm * 4 + r;
        *(float4*)&gp[row * NG + bn + tn * 8] =
            make_float4(acc[r][0], acc[r][1], acc[r][2], acc[r][3]);
        *(float4*)&gp[row * NG + bn + tn * 8 + 4] =
            make_float4(acc[r][4], acc[r][5], acc[r][6], acc[r][7]);
    }
}

// --- phase L: combine partials + biases, LSTM pointwise, output proj. ---
__device__ __forceinline__ void lstm_phase(const float* __restrict__ bih,
                                           const float* __restrict__ bhh,
                                           const float* __restrict__ Cdw,
                                           const float* __restrict__ Cdb,
                                           float* __restrict__ out, int t,
                                           char* dynsm) {
    const int cta = blockIdx.x;
    if (cta >= 128) return;
    const int half = threadIdx.x >> 8;
    const int t2 = threadIdx.x & 255;
    const int b = cta * 2 + half;
    const int warp = t2 >> 5, lane = t2 & 31;
    float* sh2 = (float*)(dynsm + half * 4096);  // 256 floats

    const int base = b * NG;
    float gi = bih[t2]       + bhh[t2];
    float gf = bih[256 + t2] + bhh[256 + t2];
    float gg = bih[512 + t2] + bhh[512 + t2];
    float go = bih[768 + t2] + bhh[768 + t2];
#pragma unroll
    for (int z = 0; z < SPK; z++) {
        const float* gp = g_gpart[z] + base;
        gi += __ldcg(&gp[t2]);
        gf += __ldcg(&gp[256 + t2]);
        gg += __ldcg(&gp[512 + t2]);
        go += __ldcg(&gp[768 + t2]);
    }

    float c2 = sigmoidf_(gf) * g_c[b * HH + t2] + sigmoidf_(gi) * tanhf(gg);
    float h2 = sigmoidf_(go) * tanhf(c2);
    g_c[b * HH + t2] = c2;
    g_inp[b * KTOT + KIH + t2] = h2;
    sh2[t2] = h2;
    NB(half);

    for (int v = warp; v < VV; v += 8) {
        const float* wr = Cdw + (size_t)v * HH;
        float s = 0.0f;
#pragma unroll
        for (int k = lane; k < HH; k += 32) s += sh2[k] * wr[k];
        s = warp_sum(s);
        if (lane == 0) {
            float val = s + Cdb[v];
            out[((size_t)b * TT + t) * VV + v] = val;
            g_inp[b * KTOT + v] = val;
        }
    }
}

// ============================================================================
// MEGAKERNEL: all 32 steps, 3 grid barriers/step (q->attn sync is flag-based).
// ============================================================================
__global__ __launch_bounds__(512, 1) void mega_kernel(
    const float* __restrict__ Hcw, const float* __restrict__ Hcb,
    const float* __restrict__ Wih, const float* __restrict__ Whh,
    const float* __restrict__ bih, const float* __restrict__ bhh,
    const float* __restrict__ Cdw, const float* __restrict__ Cdb,
    float* __restrict__ out) {
    extern __shared__ __align__(16) char dynsm[];
    __shared__ float sm_m[16], sm_s[16];

    for (int t = 0; t < TT; t++) {
        q_phase(Hcw, Hcb, dynsm);            // ctas 0..31 compute q, signal flag
        attn_phase(dynsm, sm_m, sm_s);       // prologue overlap, poll flag, run
        grid_barrier(t * 3 + 0);
        // reset q flag for next step; ordered before next increments by the
        // two grid barriers below (CTA 0 participates in both).
        if (blockIdx.x == 0 && threadIdx.x == 0) g_qdone = 0u;
        gates_phase(Wih, Whh, dynsm);
        grid_barrier(t * 3 + 1);
        lstm_phase(bih, bhh, Cdw, Cdb, out, t, dynsm);
        grid_barrier(t * 3 + 2);
    }
}

// ============================================================================
extern "C" void kernel_launch(void* const* d_in, const int* in_sizes, int n_in,
                              void* d_out, int out_size) {
    (void)in_sizes; (void)n_in; (void)out_size;
    const float* img  = (const float*)d_in[0];
    const float* tgt  = (const float*)d_in[1];
    const float* Icw  = (const float*)d_in[2];
    const float* Icb  = (const float*)d_in[3];
    const float* Hcw  = (const float*)d_in[4];
    const float* Hcb  = (const float*)d_in[5];
    const float* Wih  = (const float*)d_in[6];
    const float* Whh  = (const float*)d_in[7];
    const float* bih  = (const float*)d_in[8];
    const float* bhh  = (const float*)d_in[9];
    const float* Cdw  = (const float*)d_in[10];
    const float* Cdb  = (const float*)d_in[11];
    float* out = (float*)d_out;

    const int PROJ_SMEM = 13824 * (int)sizeof(float);  // 55296 B dynamic
    cudaFuncSetAttribute(proj_kernel, cudaFuncAttributeMaxDynamicSharedMemorySize,
                         PROJ_SMEM);
    const int MEGA_SMEM = 65536;  // 64 KB dynamic
    cudaFuncSetAttribute(mega_kernel, cudaFuncAttributeMaxDynamicSharedMemorySize,
                         MEGA_SMEM);

    proj_kernel<<<dim3((BB * PP) / 64, AA / 128), 256, PROJ_SMEM>>>(img, Icw, Icb);
    init_kernel<<<BB, 256>>>(tgt);
    mega_kernel<<<GRID, 512, MEGA_SMEM>>>(Hcw, Hcb, Wih, Whh, bih, bhh, Cdw, Cdb, out);
}

// round 16
// speedup vs baseline: 1.1177x; 1.1177x over previous
#include <cuda_runtime.h>
#include <cuda_fp16.h>
#include <mma.h>
#include <math.h>
#include <stdint.h>

using namespace nvcuda;

#define BB 256
#define PP 620
#define CC 512
#define TT 32
#define VV 140
#define HH 256
#define AA 256
#define KIH (VV + AA)         // 396
#define KTOT (VV + AA + HH)   // 652 : [x | ctx | h]
#define NG   (4 * HH)         // 1024 gates
#define NS   4                // attention cp.async ring depth (pair-stages)
#define SPK  8                // gates split-K factor
#define GRID 128              // persistent CTAs (1/SM, co-resident)
#define HREG 32768            // per-half smem region (bytes)

// proj tiling (v4): 64M x 128N tile, 32-k stages, padded ldm
#define PK   32
#define PLDM2 36

// ---------------- scratch (device globals; no allocations allowed) ----------
__device__ __half g_attn[(size_t)BB * PP * AA];   // 81.3 MB (fp16)
__device__ float  g_inp[BB * KTOT];               // packed [x | ctx | h]
__device__ float  g_c[BB * HH];
__device__ float  g_q[BB * AA];
__device__ float  g_gpart[SPK][BB * NG];          // split-K partials
// per-group pipeline counters (monotonic across graph replays)
__device__ unsigned g_ctxdone[TT][4];
__device__ unsigned g_gatesdone[TT][4];
__device__ unsigned g_statedone[TT][4];
__device__ unsigned g_round[GRID];

// ---------------- helpers ----------------
__device__ __forceinline__ float warp_sum(float v) {
#pragma unroll
    for (int o = 16; o > 0; o >>= 1) v += __shfl_xor_sync(0xFFFFFFFFu, v, o);
    return v;
}
__device__ __forceinline__ float sigmoidf_(float x) { return 1.0f / (1.0f + __expf(-x)); }
__device__ __forceinline__ unsigned smem_u32(const void* p) {
    return (unsigned)__cvta_generic_to_shared(p);
}
__device__ __forceinline__ void load8h(float* v, const __half* p) {
    uint4 u = *(const uint4*)p;
    float2 f;
    f = __half22float2(*reinterpret_cast<__half2*>(&u.x)); v[0] = f.x; v[1] = f.y;
    f = __half22float2(*reinterpret_cast<__half2*>(&u.y)); v[2] = f.x; v[3] = f.y;
    f = __half22float2(*reinterpret_cast<__half2*>(&u.z)); v[4] = f.x; v[5] = f.y;
    f = __half22float2(*reinterpret_cast<__half2*>(&u.w)); v[6] = f.x; v[7] = f.y;
}

#define CP_ASYNC16(dst32, src) \
    asm volatile("cp.async.cg.shared.global [%0], [%1], 16;" :: "r"(dst32), "l"(src))
#define CP_COMMIT() asm volatile("cp.async.commit_group;")
#define CP_WAIT(N)  asm volatile("cp.async.wait_group %0;" :: "n"(N))
// named barrier over one 256-thread half (ids 1 and 2; 0 is __syncthreads)
#define NB(half) asm volatile("bar.sync %0, 256;" :: "r"((half) + 1) : "memory")

// one poller per half, then release the half.  Producer side fenced, so after
// the bar.sync consumers may read the produced data (via L2 / __ldcg).
__device__ __forceinline__ void wait_ctr(unsigned* c, unsigned tgt, int half) {
    if ((threadIdx.x & 255) == 0) {
        volatile unsigned* f = c;
        while (*f < tgt) {}
    }
    NB(half);
}

// ============================================================================
// Kernel 1: projection  attn[m, a] = sum_c img[m, c] * Ic_w[a, c] + Ic_b[a]
// (v4, unchanged this round)
// ============================================================================
__global__ __launch_bounds__(256, 3) void proj_kernel(const float* __restrict__ img,
                                                      const float* __restrict__ Icw,
                                                      const float* __restrict__ Icb) {
    extern __shared__ __align__(16) float psm[];
    float* const smA0 = psm;
    float* const smA1 = psm + 2304;
    float* const smB0 = psm + 4608;
    float* const smB1 = psm + 9216;

    const int bm = blockIdx.x * 64;
    const int bn = blockIdx.y * 128;
    const int tid = threadIdx.x;
    const int warp = tid >> 5, lane = tid & 31;
    const int warp_m = warp & 1;
    const int warp_n = warp >> 1;
    const int NKS = CC / PK;

    auto issue = [&](int ks, int buf) {
        const int k0 = ks * PK;
        float* sA = buf ? smA1 : smA0;
        float* sB = buf ? smB1 : smB0;
#pragma unroll
        for (int j = 0; j < 2; j++) {
            int idx = tid + j * 256;
            int row = idx >> 3, q = idx & 7;
            CP_ASYNC16(smem_u32(&sA[row * PLDM2 + q * 4]),
                       img + (size_t)(bm + row) * CC + k0 + q * 4);
        }
#pragma unroll
        for (int j = 0; j < 4; j++) {
            int idx = tid + j * 256;
            int row = idx >> 3, q = idx & 7;
            CP_ASYNC16(smem_u32(&sB[row * PLDM2 + q * 4]),
                       Icw + (size_t)(bn + row) * CC + k0 + q * 4);
        }
        CP_COMMIT();
    };

    wmma::fragment<wmma::accumulator, 16, 16, 8, float> acc[2][2];
#pragma unroll
    for (int mi = 0; mi < 2; mi++)
#pragma unroll
        for (int nj = 0; nj < 2; nj++) wmma::fill_fragment(acc[mi][nj], 0.0f);

    issue(0, 0);
    issue(1, 1);

    for (int ks = 0; ks < NKS; ks++) {
        if (ks + 1 < NKS) { CP_WAIT(1); } else { CP_WAIT(0); }
        __syncthreads();
        const int buf = ks & 1;
        const float* sA = buf ? smA1 : smA0;
        const float* sB = buf ? smB1 : smB0;
#pragma unroll
        for (int kk = 0; kk < PK; kk += 8) {
            wmma::fragment<wmma::matrix_a, 16, 16, 8, wmma::precision::tf32, wmma::row_major> fa[2];
            wmma::fragment<wmma::matrix_b, 16, 16, 8, wmma::precision::tf32, wmma::col_major> fb[2];
#pragma unroll
            for (int mi = 0; mi < 2; mi++)
                wmma::load_matrix_sync(fa[mi], &sA[(warp_m * 32 + mi * 16) * PLDM2 + kk], PLDM2);
#pragma unroll
            for (int nj = 0; nj < 2; nj++)
                wmma::load_matrix_sync(fb[nj], &sB[(warp_n * 32 + nj * 16) * PLDM2 + kk], PLDM2);
#pragma unroll
            for (int mi = 0; mi < 2; mi++)
#pragma unroll
                for (int nj = 0; nj < 2; nj++)
                    wmma::mma_sync(acc[mi][nj], fa[mi], fb[nj], acc[mi][nj]);
        }
        __syncthreads();
        if (ks + 2 < NKS) issue(ks + 2, buf);
    }

    __syncthreads();
    float* patch = psm + warp * 256;
    const int prow = lane >> 1, pc0 = (lane & 1) * 8;
#pragma unroll
    for (int mi = 0; mi < 2; mi++) {
#pragma unroll
        for (int nj = 0; nj < 2; nj++) {
            wmma::store_matrix_sync(patch, acc[mi][nj], 16, wmma::mem_row_major);
            __syncwarp();
            const int gm = bm + warp_m * 32 + mi * 16 + prow;
            const int gc = bn + warp_n * 32 + nj * 16 + pc0;
            __half2 h2s[4];
#pragma unroll
            for (int j = 0; j < 4; j++) {
                float v0 = patch[prow * 16 + pc0 + 2 * j]     + Icb[gc + 2 * j];
                float v1 = patch[prow * 16 + pc0 + 2 * j + 1] + Icb[gc + 2 * j + 1];
                h2s[j] = __floats2half2_rn(v0, v1);
            }
            *(uint4*)&g_attn[(size_t)gm * AA + gc] = *(uint4*)h2s;
            __syncwarp();
        }
    }
}

// ============================================================================
// Kernel 2: init  g_inp = [x0 | 0 | 0], c = 0, q0 = Hcb (h0 = 0).
// ============================================================================
__global__ void init_kernel(const float* __restrict__ targets,
                            const float* __restrict__ Hcb) {
    const int b = blockIdx.x;
    const int tid = threadIdx.x;
    for (int k = tid; k < KTOT; k += 256)
        g_inp[b * KTOT + k] = (k < VV) ? targets[(size_t)b * TT * VV + k] : 0.0f;
    g_c[b * HH + tid] = 0.0f;
    g_q[b * AA + tid] = Hcb[tid];
}

// ============================================================================
// MEGAKERNEL: 128 CTAs x 512 threads = 256 half-units; group g = cta>>5 owns
// batches [64g, 64g+64).  Per-group counter pipeline, ZERO grid barriers.
// Each half owns smem region dynsm + half*HREG (32 KB) — halves progress
// independently, never sharing smem.
// ============================================================================

// --- attention (flash, warp-autonomous; half handles b = cta*2 + half) ---
__device__ __forceinline__ void attn_phase(char* dynsm, float* sm_m, float* sm_s,
                                           int t, int g, unsigned tgt) {
    const int tid = threadIdx.x;
    const int w = tid >> 5, l = tid & 31;
    const int half = w >> 3, wg = w & 7;
    const int b = blockIdx.x * 2 + half;
    const __half* attb = g_attn + (size_t)b * PP * AA;
    char* hbase = dynsm + half * HREG;
    __half* ring = (__half*)(hbase) + wg * (NS * 2 * AA);   // 4KB per warp

    const int nrow = (PP - wg + 7) >> 3;   // 78 (wg<4) or 77
    const int npair = 39;

    // prologue (g_attn is const — safe before the state wait)
#pragma unroll
    for (int it = 0; it < NS; it++) {
        CP_ASYNC16(smem_u32(ring + (it * 2 + 0) * AA + l * 8),
                   attb + (size_t)(wg + (2 * it) * 8) * AA + l * 8);
        CP_ASYNC16(smem_u32(ring + (it * 2 + 1) * AA + l * 8),
                   attb + (size_t)(wg + (2 * it + 1) * 8) * AA + l * 8);
        CP_COMMIT();
    }

    // wait for this group's previous-step state (h, x, q) — skip at t=0 (init)
    if (t > 0) wait_ctr(&g_statedone[t - 1][g], tgt, half);

    float q8[8];
    {
        float4 qa = __ldcg((const float4*)&g_q[b * AA + l * 8]);
        float4 qb = __ldcg((const float4*)&g_q[b * AA + l * 8 + 4]);
        q8[0] = qa.x; q8[1] = qa.y; q8[2] = qa.z; q8[3] = qa.w;
        q8[4] = qb.x; q8[5] = qb.y; q8[6] = qb.z; q8[7] = qb.w;
    }

    const float scale = 0.0625f;
    float m = -1e30f, ssum = 0.0f;
    float ctx[8] = {0.f, 0.f, 0.f, 0.f, 0.f, 0.f, 0.f, 0.f};

    for (int it = 0; it < npair; it++) {
        const int s = it & (NS - 1);
        CP_WAIT(NS - 1);

        float v0[8], v1[8];
        load8h(v0, ring + (s * 2 + 0) * AA + l * 8);
        load8h(v1, ring + (s * 2 + 1) * AA + l * 8);

        float d0 = 0.f, d1 = 0.f;
#pragma unroll
        for (int j = 0; j < 8; j++) { d0 = fmaf(q8[j], v0[j], d0); d1 = fmaf(q8[j], v1[j], d1); }
        d0 = warp_sum(d0);
        d1 = warp_sum(d1);

        const bool val1 = (2 * it + 1) < nrow;
        float sc0 = d0 * scale;
        float sc1 = val1 ? d1 * scale : -1e30f;
        float mn = fmaxf(m, fmaxf(sc0, sc1));
        float fac = __expf(m - mn);
        float e0 = __expf(sc0 - mn);
        float e1 = val1 ? __expf(sc1 - mn) : 0.0f;
        ssum = ssum * fac + e0 + e1;
        if (val1) {
#pragma unroll
            for (int j = 0; j < 8; j++)
                ctx[j] = fmaf(e1, v1[j], fmaf(e0, v0[j], ctx[j] * fac));
        } else {
#pragma unroll
            for (int j = 0; j < 8; j++)
                ctx[j] = fmaf(e0, v0[j], ctx[j] * fac);
        }
        m = mn;

        const int nit = it + NS;
        if (nit < npair) {
            const int i0 = 2 * nit, i1 = i0 + 1;
            CP_ASYNC16(smem_u32(ring + (s * 2 + 0) * AA + l * 8),
                       attb + (size_t)(wg + i0 * 8) * AA + l * 8);
            if (i1 < nrow)
                CP_ASYNC16(smem_u32(ring + (s * 2 + 1) * AA + l * 8),
                           attb + (size_t)(wg + i1 * 8) * AA + l * 8);
        }
        CP_COMMIT();
    }
    CP_WAIT(0);

    NB(half);
    float* cbuf = (float*)hbase;  // overlays this half's rings
    *(float4*)&cbuf[wg * AA + l * 8]     = make_float4(ctx[0], ctx[1], ctx[2], ctx[3]);
    *(float4*)&cbuf[wg * AA + l * 8 + 4] = make_float4(ctx[4], ctx[5], ctx[6], ctx[7]);
    if (l == 0) { sm_m[w] = m; sm_s[w] = ssum; }
    NB(half);

    const int t2 = tid & 255;  // column a
    float M = -1e30f;
#pragma unroll
    for (int ww = 0; ww < 8; ww++) M = fmaxf(M, sm_m[half * 8 + ww]);
    float S = 0.f, C = 0.f;
#pragma unroll
    for (int ww = 0; ww < 8; ww++) {
        float ef = __expf(sm_m[half * 8 + ww] - M);
        S += ef * sm_s[half * 8 + ww];
        C = fmaf(ef, cbuf[ww * AA + t2], C);
    }
    g_inp[b * KTOT + VV + t2] = C / S;
    __threadfence();
    NB(half);   // all ctx writes fenced AND all cbuf reads done before signal
    if (t2 == 0) atomicAdd(&g_ctxdone[t][g], 1u);
}

// --- gates GEMM.  Unit u = cta*2 + half: z=u&7, bn=((u>>3)&7)*128,
// bm=(u>>6)*64 == g*64 (unit's m-rows are its own group's batches). ---
__device__ __forceinline__ void gates_phase(const float* __restrict__ Wih,
                                            const float* __restrict__ Whh,
                                            char* dynsm, int t, int g, unsigned tgt) {
    const int half = threadIdx.x >> 8;
    const int t2 = threadIdx.x & 255;
    const int u = blockIdx.x * 2 + half;
    const int z  = u & 7;
    const int bn = ((u >> 3) & 7) * 128;
    const int bm = (u >> 6) * 64;

    // wait for this group's ctx (attn of step t); h/x covered transitively.
    wait_ctr(&g_ctxdone[t][g], tgt, half);

    float* sA = (float*)(dynsm + half * HREG);   // [16][68]
    float* sB = sA + 16 * 68;                    // [16][132]
    const int tm = t2 & 15, tn = t2 >> 4;
    const int arow = t2 >> 2, akq = t2 & 3;

    float acc[4][8] = {};
    float4 aR, bR0, bR1;

    auto loadP = [&](int k0) {
        const float4 z4 = make_float4(0.f, 0.f, 0.f, 0.f);
        int ka = k0 + akq * 4;
        aR = (ka + 3 < KTOT) ? __ldcg((const float4*)&g_inp[(bm + arow) * KTOT + ka]) : z4;
#pragma unroll
        for (int i = 0; i < 2; i++) {
            int idx = t2 + i * 256;
            int n = bn + (idx >> 2);
            int kb = k0 + (idx & 3) * 4;
            float4 v = z4;
            if (kb + 3 < KTOT) {
                if (kb + 3 < KIH) v = *(const float4*)&Wih[(size_t)n * KIH + kb];
                else              v = *(const float4*)&Whh[(size_t)n * HH + (kb - KIH)];
            }
            if (i == 0) bR0 = v; else bR1 = v;
        }
    };

    loadP(z * 16);

    for (int panel = z; panel * 16 < KTOT; panel += SPK) {
        sA[(akq * 4 + 0) * 68 + arow] = aR.x; sA[(akq * 4 + 1) * 68 + arow] = aR.y;
        sA[(akq * 4 + 2) * 68 + arow] = aR.z; sA[(akq * 4 + 3) * 68 + arow] = aR.w;
#pragma unroll
        for (int i = 0; i < 2; i++) {
            int idx = t2 + i * 256;
            int nl = idx >> 2, kq = idx & 3;
            float4 v = (i == 0) ? bR0 : bR1;
            sB[(kq * 4 + 0) * 132 + nl] = v.x; sB[(kq * 4 + 1) * 132 + nl] = v.y;
            sB[(kq * 4 + 2) * 132 + nl] = v.z; sB[(kq * 4 + 3) * 132 + nl] = v.w;
        }
        NB(half);

        if ((panel + SPK) * 16 < KTOT) loadP((panel + SPK) * 16);

#pragma unroll
        for (int kk = 0; kk < 16; kk++) {
            float4 a4  = *(const float4*)&sA[kk * 68 + tm * 4];
            float4 b4a = *(const float4*)&sB[kk * 132 + tn * 8];
            float4 b4b = *(const float4*)&sB[kk * 132 + tn * 8 + 4];
            const float ar[4] = {a4.x, a4.y, a4.z, a4.w};
            const float br[8] = {b4a.x, b4a.y, b4a.z, b4a.w, b4b.x, b4b.y, b4b.z, b4b.w};
#pragma unroll
            for (int r = 0; r < 4; r++)
#pragma unroll
                for (int c = 0; c < 8; c++)
                    acc[r][c] = fmaf(ar[r], br[c], acc[r][c]);
        }
        NB(half);
    }

    float* gp = g_gpart[z];
#pragma unroll
    for (int r = 0; r < 4; r++) {
        int row = bm + tm * 4 + r;
        *(float4*)&gp[row * NG + bn + tn * 8] =
            make_float4(acc[r][0], acc[r][1], acc[r][2], acc[r][3]);
        *(float4*)&gp[row * NG + bn + tn * 8 + 4] =
            make_float4(acc[r][4], acc[r][5], acc[r][6], acc[r][7]);
    }
    __threadfence();
    NB(half);   // gpart fenced; sA/sB reads done before lstm overwrites region
    if (t2 == 0) atomicAdd(&g_gatesdone[t][g], 1u);
}

// --- lstm: combine partials + biases, pointwise, output proj, AND q_{t+1}. ---
__device__ __forceinline__ void lstm_phase(const float* __restrict__ bih,
                                           const float* __restrict__ bhh,
                                           const float* __restrict__ Cdw,
                                           const float* __restrict__ Cdb,
                                           const float* __restrict__ Hcw,
                                           const float* __restrict__ Hcb,
                                           float* __restrict__ out, int t,
                                           int g, unsigned tgt, char* dynsm) {
    const int half = threadIdx.x >> 8;
    const int t2 = threadIdx.x & 255;
    const int b = blockIdx.x * 2 + half;
    const int warp = t2 >> 5, lane = t2 & 31;
    float* sh2 = (float*)(dynsm + half * HREG);  // 256 floats

    // wait for this group's gates partials
    wait_ctr(&g_gatesdone[t][g], tgt, half);

    const int base = b * NG;
    float gi = bih[t2]       + bhh[t2];
    float gf = bih[256 + t2] + bhh[256 + t2];
    float gg = bih[512 + t2] + bhh[512 + t2];
    float go = bih[768 + t2] + bhh[768 + t2];
#pragma unroll
    for (int z = 0; z < SPK; z++) {
        const float* gp = g_gpart[z] + base;
        gi += __ldcg(&gp[t2]);
        gf += __ldcg(&gp[256 + t2]);
        gg += __ldcg(&gp[512 + t2]);
        go += __ldcg(&gp[768 + t2]);
    }

    float c2 = sigmoidf_(gf) * g_c[b * HH + t2] + sigmoidf_(gi) * tanhf(gg);
    float h2 = sigmoidf_(go) * tanhf(c2);
    g_c[b * HH + t2] = c2;                 // same CTA owns b every step (L1 ok)
    g_inp[b * KTOT + KIH + t2] = h2;       // h for next step
    sh2[t2] = h2;
    NB(half);

    // ---- q_{t+1} = h2 @ Hcw^T + Hcb : warp handles 32 outputs, 2 at a time,
    // lanes split k (coalesced 128B rows), h chunk preloaded. ----
    {
        float h8[8];
#pragma unroll
        for (int i = 0; i < 8; i++) h8[i] = sh2[lane * 8 + i];
        const int jbase = warp * 32;
#pragma unroll 4
        for (int jj = 0; jj < 32; jj += 2) {
            const int j0 = jbase + jj, j1 = j0 + 1;
            const float4* r0 = (const float4*)(Hcw + (size_t)j0 * HH);
            const float4* r1 = (const float4*)(Hcw + (size_t)j1 * HH);
            float4 a0 = r0[lane * 2], b0 = r0[lane * 2 + 1];
            float4 a1 = r1[lane * 2], b1 = r1[lane * 2 + 1];
            float s0 = h8[0] * a0.x + h8[1] * a0.y + h8[2] * a0.z + h8[3] * a0.w
                     + h8[4] * b0.x + h8[5] * b0.y + h8[6] * b0.z + h8[7] * b0.w;
            float s1 = h8[0] * a1.x + h8[1] * a1.y + h8[2] * a1.z + h8[3] * a1.w
                     + h8[4] * b1.x + h8[5] * b1.y + h8[6] * b1.z + h8[7] * b1.w;
            s0 = warp_sum(s0);
            s1 = warp_sum(s1);
            if (lane == 0) {
                g_q[b * AA + j0] = s0 + Hcb[j0];
                g_q[b * AA + j1] = s1 + Hcb[j1];
            }
        }
    }

    // ---- out[b, t, :] = h2 @ Cdw^T + Cdb ; also x for next step ----
    for (int v = warp; v < VV; v += 8) {
        const float* wr = Cdw + (size_t)v * HH;
        float s = 0.0f;
#pragma unroll
        for (int k = lane; k < HH; k += 32) s += sh2[k] * wr[k];
        s = warp_sum(s);
        if (lane == 0) {
            float val = s + Cdb[v];
            out[((size_t)b * TT + t) * VV + v] = val;
            g_inp[b * KTOT + v] = val;
        }
    }

    __threadfence();
    NB(half);   // h/x/q/out fenced; sh2 reads done before next attn's ring writes
    if (t2 == 0) atomicAdd(&g_statedone[t][g], 1u);
}

// ============================================================================
__global__ __launch_bounds__(512, 1) void mega_kernel(
    const float* __restrict__ Hcw, const float* __restrict__ Hcb,
    const float* __restrict__ Wih, const float* __restrict__ Whh,
    const float* __restrict__ bih, const float* __restrict__ bhh,
    const float* __restrict__ Cdw, const float* __restrict__ Cdb,
    float* __restrict__ out) {
    extern __shared__ __align__(16) char dynsm[];
    __shared__ float sm_m[16], sm_s[16];
    __shared__ unsigned s_r;

    if (threadIdx.x == 0) s_r = atomicAdd(&g_round[blockIdx.x], 1u);
    __syncthreads();
    const unsigned tgt = 64u * (s_r + 1u);   // 64 half-signals per group/step
    const int g = blockIdx.x >> 5;           // batch group 0..3

    for (int t = 0; t < TT; t++) {
        attn_phase(dynsm, sm_m, sm_s, t, g, tgt);
        gates_phase(Wih, Whh, dynsm, t, g, tgt);
        lstm_phase(bih, bhh, Cdw, Cdb, Hcw, Hcb, out, t, g, tgt, dynsm);
    }
}

// ============================================================================
extern "C" void kernel_launch(void* const* d_in, const int* in_sizes, int n_in,
                              void* d_out, int out_size) {
    (void)in_sizes; (void)n_in; (void)out_size;
    const float* img  = (const float*)d_in[0];
    const float* tgt  = (const float*)d_in[1];
    const float* Icw  = (const float*)d_in[2];
    const float* Icb  = (const float*)d_in[3];
    const float* Hcw  = (const float*)d_in[4];
    const float* Hcb  = (const float*)d_in[5];
    const float* Wih  = (const float*)d_in[6];
    const float* Whh  = (const float*)d_in[7];
    const float* bih  = (const float*)d_in[8];
    const float* bhh  = (const float*)d_in[9];
    const float* Cdw  = (const float*)d_in[10];
    const float* Cdb  = (const float*)d_in[11];
    float* out = (float*)d_out;

    const int PROJ_SMEM = 13824 * (int)sizeof(float);  // 55296 B dynamic
    cudaFuncSetAttribute(proj_kernel, cudaFuncAttributeMaxDynamicSharedMemorySize,
                         PROJ_SMEM);
    const int MEGA_SMEM = 65536;  // 64 KB dynamic (2 x 32 KB half-regions)
    cudaFuncSetAttribute(mega_kernel, cudaFuncAttributeMaxDynamicSharedMemorySize,
                         MEGA_SMEM);

    proj_kernel<<<dim3((BB * PP) / 64, AA / 128), 256, PROJ_SMEM>>>(img, Icw, Icb);
    init_kernel<<<BB, 256>>>(tgt, Hcb);
    mega_kernel<<<GRID, 512, MEGA_SMEM>>>(Hcw, Hcb, Wih, Whh, bih, bhh, Cdw, Cdb, out);
}

// round 17
// speedup vs baseline: 1.4897x; 1.3328x over previous
#include <cuda_runtime.h>
#include <cuda_fp16.h>
#include <mma.h>
#include <math.h>
#include <stdint.h>

using namespace nvcuda;

#define BB 256
#define PP 620
#define CC 512
#define TT 32
#define VV 140
#define HH 256
#define AA 256
#define KIH (VV + AA)         // 396
#define KTOT (VV + AA + HH)   // 652 : [x | ctx | h]
#define NG   (4 * HH)         // 1024 gates
#define NS   4                // attention cp.async ring depth (pair-stages)
#define SPK  8                // gates split-K factor
#define GRID 128              // persistent CTAs (1/SM, co-resident)
#define HREG 32768            // per-half smem region (bytes)

// proj tiling (v5, fp16): 64M x 128N tile, 32-k stages, padded ldm (halfs)
#define PKH   32
#define PLDMH 40              // 40 halfs = 80B row stride -> conflict-free frag loads

// ---------------- scratch (device globals; no allocations allowed) ----------
__device__ __half g_attn[(size_t)BB * PP * AA];   // 81.3 MB (fp16)
__device__ float  g_inp[BB * KTOT];               // packed [x | ctx | h]
__device__ float  g_c[BB * HH];
__device__ float  g_q[BB * AA];
__device__ float  g_gpart[SPK][BB * NG];          // split-K partials
// per-group pipeline counters (monotonic across graph replays)
__device__ unsigned g_ctxdone[TT][4];
__device__ unsigned g_gatesdone[TT][4];
__device__ unsigned g_statedone[TT][4];
__device__ unsigned g_round[GRID];

// ---------------- helpers ----------------
__device__ __forceinline__ float warp_sum(float v) {
#pragma unroll
    for (int o = 16; o > 0; o >>= 1) v += __shfl_xor_sync(0xFFFFFFFFu, v, o);
    return v;
}
__device__ __forceinline__ float sigmoidf_(float x) { return 1.0f / (1.0f + __expf(-x)); }
__device__ __forceinline__ unsigned smem_u32(const void* p) {
    return (unsigned)__cvta_generic_to_shared(p);
}
__device__ __forceinline__ void load8h(float* v, const __half* p) {
    uint4 u = *(const uint4*)p;
    float2 f;
    f = __half22float2(*reinterpret_cast<__half2*>(&u.x)); v[0] = f.x; v[1] = f.y;
    f = __half22float2(*reinterpret_cast<__half2*>(&u.y)); v[2] = f.x; v[3] = f.y;
    f = __half22float2(*reinterpret_cast<__half2*>(&u.z)); v[4] = f.x; v[5] = f.y;
    f = __half22float2(*reinterpret_cast<__half2*>(&u.w)); v[6] = f.x; v[7] = f.y;
}

#define CP_ASYNC16(dst32, src) \
    asm volatile("cp.async.cg.shared.global [%0], [%1], 16;" :: "r"(dst32), "l"(src))
#define CP_COMMIT() asm volatile("cp.async.commit_group;")
#define CP_WAIT(N)  asm volatile("cp.async.wait_group %0;" :: "n"(N))
// named barrier over one 256-thread half (ids 1 and 2; 0 is __syncthreads)
#define NB(half) asm volatile("bar.sync %0, 256;" :: "r"((half) + 1) : "memory")

// one poller per half, then release the half.
__device__ __forceinline__ void wait_ctr(unsigned* c, unsigned tgt, int half) {
    if ((threadIdx.x & 255) == 0) {
        volatile unsigned* f = c;
        while (*f < tgt) {}
    }
    NB(half);
}

// ============================================================================
// Kernel 1: projection  attn[m, a] = sum_c img[m, c] * Ic_w[a, c] + Ic_b[a]
// v5: fp16 wmma 16x16x16 (2x tensor rate vs tf32, same 10-bit mantissa).
// 64M x 128N tiles, 32-k stages; fp32 loaded via LDG into registers, converted
// to fp16 and stored to smem (register double buffering -> ONE sync/stage).
// 8 warps in 2(m) x 4(n); warp tile 32x32 = 2x2 fragments.
// Dynamic smem 30720 B (fp16 tiles); epilogue float patches overlay the tiles.
// ============================================================================
__global__ __launch_bounds__(256, 3) void proj_kernel(const float* __restrict__ img,
                                                      const float* __restrict__ Icw,
                                                      const float* __restrict__ Icb) {
    extern __shared__ __align__(16) __half hsm[];
    __half* const hA0 = hsm;            // 64*40 = 2560 halfs
    __half* const hA1 = hsm + 2560;
    __half* const hB0 = hsm + 5120;     // 128*40 = 5120 halfs
    __half* const hB1 = hsm + 10240;    // total 15360 halfs = 30720 B

    const int bm = blockIdx.x * 64;
    const int bn = blockIdx.y * 128;
    const int tid = threadIdx.x;
    const int warp = tid >> 5, lane = tid & 31;
    const int warp_m = warp & 1;   // 2 groups of 32 rows
    const int warp_n = warp >> 1;  // 4 groups of 32 cols
    const int NKS = CC / PKH;      // 16 k-stages

    const int arow = tid >> 2, aq = tid & 3;   // A: 64 rows x 4 chunks of 8

    float4 aS0, aS1, bS[4];

    auto loadregs = [&](int ks) {
        const int k0 = ks * PKH;
        {
            const float* p = img + (size_t)(bm + arow) * CC + k0 + aq * 8;
            aS0 = *(const float4*)p;
            aS1 = *(const float4*)(p + 4);
        }
#pragma unroll
        for (int j = 0; j < 2; j++) {
            int idx = tid + j * 256;
            int row = idx >> 2, q = idx & 3;
            const float* p = Icw + (size_t)(bn + row) * CC + k0 + q * 8;
            bS[j * 2]     = *(const float4*)p;
            bS[j * 2 + 1] = *(const float4*)(p + 4);
        }
    };
    auto conv8 = [&](float4 u, float4 v, __half* dst) {
        __half2 h[4];
        h[0] = __floats2half2_rn(u.x, u.y);
        h[1] = __floats2half2_rn(u.z, u.w);
        h[2] = __floats2half2_rn(v.x, v.y);
        h[3] = __floats2half2_rn(v.z, v.w);
        *(uint4*)dst = *(uint4*)h;
    };
    auto storeconv = [&](int buf) {
        __half* sA = buf ? hA1 : hA0;
        __half* sB = buf ? hB1 : hB0;
        conv8(aS0, aS1, &sA[arow * PLDMH + aq * 8]);
#pragma unroll
        for (int j = 0; j < 2; j++) {
            int idx = tid + j * 256;
            int row = idx >> 2, q = idx & 3;
            conv8(bS[j * 2], bS[j * 2 + 1], &sB[row * PLDMH + q * 8]);
        }
    };

    wmma::fragment<wmma::accumulator, 16, 16, 16, float> acc[2][2];
#pragma unroll
    for (int mi = 0; mi < 2; mi++)
#pragma unroll
        for (int nj = 0; nj < 2; nj++) wmma::fill_fragment(acc[mi][nj], 0.0f);

    loadregs(0);
    storeconv(0);
    loadregs(1);
    __syncthreads();

    for (int ks = 0; ks < NKS; ks++) {
        const __half* sA = (ks & 1) ? hA1 : hA0;
        const __half* sB = (ks & 1) ? hB1 : hB0;
#pragma unroll
        for (int kk = 0; kk < PKH; kk += 16) {
            wmma::fragment<wmma::matrix_a, 16, 16, 16, half, wmma::row_major> fa[2];
            wmma::fragment<wmma::matrix_b, 16, 16, 16, half, wmma::col_major> fb[2];
#pragma unroll
            for (int mi = 0; mi < 2; mi++)
                wmma::load_matrix_sync(fa[mi], &sA[(warp_m * 32 + mi * 16) * PLDMH + kk], PLDMH);
#pragma unroll
            for (int nj = 0; nj < 2; nj++)
                wmma::load_matrix_sync(fb[nj], &sB[(warp_n * 32 + nj * 16) * PLDMH + kk], PLDMH);
#pragma unroll
            for (int mi = 0; mi < 2; mi++)
#pragma unroll
                for (int nj = 0; nj < 2; nj++)
                    wmma::mma_sync(acc[mi][nj], fa[mi], fb[nj], acc[mi][nj]);
        }
        if (ks + 1 < NKS) storeconv((ks + 1) & 1);   // other buffer: safe
        __syncthreads();
        if (ks + 2 < NKS) loadregs(ks + 2);
    }

    // ---- epilogue: frag -> float patch (overlays fp16 tiles) -> +bias -> fp16 ----
    __syncthreads();
    float* patch = (float*)hsm + warp * 256;   // 8 warps * 1KB = 8KB <= 30KB
    const int prow = lane >> 1, pc0 = (lane & 1) * 8;
#pragma unroll
    for (int mi = 0; mi < 2; mi++) {
#pragma unroll
        for (int nj = 0; nj < 2; nj++) {
            wmma::store_matrix_sync(patch, acc[mi][nj], 16, wmma::mem_row_major);
            __syncwarp();
            const int gm = bm + warp_m * 32 + mi * 16 + prow;
            const int gc = bn + warp_n * 32 + nj * 16 + pc0;
            __half2 h2s[4];
#pragma unroll
            for (int j = 0; j < 4; j++) {
                float v0 = patch[prow * 16 + pc0 + 2 * j]     + Icb[gc + 2 * j];
                float v1 = patch[prow * 16 + pc0 + 2 * j + 1] + Icb[gc + 2 * j + 1];
                h2s[j] = __floats2half2_rn(v0, v1);
            }
            *(uint4*)&g_attn[(size_t)gm * AA + gc] = *(uint4*)h2s;
            __syncwarp();
        }
    }
}

// ============================================================================
// Kernel 2: init  g_inp = [x0 | 0 | 0], c = 0, q0 = Hcb (h0 = 0).
// ============================================================================
__global__ void init_kernel(const float* __restrict__ targets,
                            const float* __restrict__ Hcb) {
    const int b = blockIdx.x;
    const int tid = threadIdx.x;
    for (int k = tid; k < KTOT; k += 256)
        g_inp[b * KTOT + k] = (k < VV) ? targets[(size_t)b * TT * VV + k] : 0.0f;
    g_c[b * HH + tid] = 0.0f;
    g_q[b * AA + tid] = Hcb[tid];
}

// ============================================================================
// MEGAKERNEL: 128 CTAs x 512 threads; group g = cta>>5 owns batches
// [64g, 64g+64).  Per-group counter pipeline, zero grid barriers.
// ============================================================================

// --- attention (flash, warp-autonomous; half handles b = cta*2 + half) ---
__device__ __forceinline__ void attn_phase(char* dynsm, float* sm_m, float* sm_s,
                                           int t, int g, unsigned tgt) {
    const int tid = threadIdx.x;
    const int w = tid >> 5, l = tid & 31;
    const int half = w >> 3, wg = w & 7;
    const int b = blockIdx.x * 2 + half;
    const __half* attb = g_attn + (size_t)b * PP * AA;
    char* hbase = dynsm + half * HREG;
    __half* ring = (__half*)(hbase) + wg * (NS * 2 * AA);   // 4KB per warp

    const int nrow = (PP - wg + 7) >> 3;   // 78 (wg<4) or 77
    const int npair = 39;

    // prologue (g_attn is const — safe before the state wait)
#pragma unroll
    for (int it = 0; it < NS; it++) {
        CP_ASYNC16(smem_u32(ring + (it * 2 + 0) * AA + l * 8),
                   attb + (size_t)(wg + (2 * it) * 8) * AA + l * 8);
        CP_ASYNC16(smem_u32(ring + (it * 2 + 1) * AA + l * 8),
                   attb + (size_t)(wg + (2 * it + 1) * 8) * AA + l * 8);
        CP_COMMIT();
    }

    if (t > 0) wait_ctr(&g_statedone[t - 1][g], tgt, half);

    float q8[8];
    {
        float4 qa = __ldcg((const float4*)&g_q[b * AA + l * 8]);
        float4 qb = __ldcg((const float4*)&g_q[b * AA + l * 8 + 4]);
        q8[0] = qa.x; q8[1] = qa.y; q8[2] = qa.z; q8[3] = qa.w;
        q8[4] = qb.x; q8[5] = qb.y; q8[6] = qb.z; q8[7] = qb.w;
    }

    const float scale = 0.0625f;
    float m = -1e30f, ssum = 0.0f;
    float ctx[8] = {0.f, 0.f, 0.f, 0.f, 0.f, 0.f, 0.f, 0.f};

    for (int it = 0; it < npair; it++) {
        const int s = it & (NS - 1);
        CP_WAIT(NS - 1);

        float v0[8], v1[8];
        load8h(v0, ring + (s * 2 + 0) * AA + l * 8);
        load8h(v1, ring + (s * 2 + 1) * AA + l * 8);

        float d0 = 0.f, d1 = 0.f;
#pragma unroll
        for (int j = 0; j < 8; j++) { d0 = fmaf(q8[j], v0[j], d0); d1 = fmaf(q8[j], v1[j], d1); }
        d0 = warp_sum(d0);
        d1 = warp_sum(d1);

        const bool val1 = (2 * it + 1) < nrow;
        float sc0 = d0 * scale;
        float sc1 = val1 ? d1 * scale : -1e30f;
        float mn = fmaxf(m, fmaxf(sc0, sc1));
        float fac = __expf(m - mn);
        float e0 = __expf(sc0 - mn);
        float e1 = val1 ? __expf(sc1 - mn) : 0.0f;
        ssum = ssum * fac + e0 + e1;
        if (val1) {
#pragma unroll
            for (int j = 0; j < 8; j++)
                ctx[j] = fmaf(e1, v1[j], fmaf(e0, v0[j], ctx[j] * fac));
        } else {
#pragma unroll
            for (int j = 0; j < 8; j++)
                ctx[j] = fmaf(e0, v0[j], ctx[j] * fac);
        }
        m = mn;

        const int nit = it + NS;
        if (nit < npair) {
            const int i0 = 2 * nit, i1 = i0 + 1;
            CP_ASYNC16(smem_u32(ring + (s * 2 + 0) * AA + l * 8),
                       attb + (size_t)(wg + i0 * 8) * AA + l * 8);
            if (i1 < nrow)
                CP_ASYNC16(smem_u32(ring + (s * 2 + 1) * AA + l * 8),
                           attb + (size_t)(wg + i1 * 8) * AA + l * 8);
        }
        CP_COMMIT();
    }
    CP_WAIT(0);

    NB(half);
    float* cbuf = (float*)hbase;  // overlays this half's rings
    *(float4*)&cbuf[wg * AA + l * 8]     = make_float4(ctx[0], ctx[1], ctx[2], ctx[3]);
    *(float4*)&cbuf[wg * AA + l * 8 + 4] = make_float4(ctx[4], ctx[5], ctx[6], ctx[7]);
    if (l == 0) { sm_m[w] = m; sm_s[w] = ssum; }
    NB(half);

    const int t2 = tid & 255;  // column a
    float M = -1e30f;
#pragma unroll
    for (int ww = 0; ww < 8; ww++) M = fmaxf(M, sm_m[half * 8 + ww]);
    float S = 0.f, C = 0.f;
#pragma unroll
    for (int ww = 0; ww < 8; ww++) {
        float ef = __expf(sm_m[half * 8 + ww] - M);
        S += ef * sm_s[half * 8 + ww];
        C = fmaf(ef, cbuf[ww * AA + t2], C);
    }
    g_inp[b * KTOT + VV + t2] = C / S;
    __threadfence();
    NB(half);
    if (t2 == 0) atomicAdd(&g_ctxdone[t][g], 1u);
}

// --- gates GEMM.  Unit u = cta*2 + half: z=u&7, bn=((u>>3)&7)*128, bm=g*64 ---
__device__ __forceinline__ void gates_phase(const float* __restrict__ Wih,
                                            const float* __restrict__ Whh,
                                            char* dynsm, int t, int g, unsigned tgt) {
    const int half = threadIdx.x >> 8;
    const int t2 = threadIdx.x & 255;
    const int u = blockIdx.x * 2 + half;
    const int z  = u & 7;
    const int bn = ((u >> 3) & 7) * 128;
    const int bm = (u >> 6) * 64;

    wait_ctr(&g_ctxdone[t][g], tgt, half);

    float* sA = (float*)(dynsm + half * HREG);   // [16][68]
    float* sB = sA + 16 * 68;                    // [16][132]
    const int tm = t2 & 15, tn = t2 >> 4;
    const int arow = t2 >> 2, akq = t2 & 3;

    float acc[4][8] = {};
    float4 aR, bR0, bR1;

    auto loadP = [&](int k0) {
        const float4 z4 = make_float4(0.f, 0.f, 0.f, 0.f);
        int ka = k0 + akq * 4;
        aR = (ka + 3 < KTOT) ? __ldcg((const float4*)&g_inp[(bm + arow) * KTOT + ka]) : z4;
#pragma unroll
        for (int i = 0; i < 2; i++) {
            int idx = t2 + i * 256;
            int n = bn + (idx >> 2);
            int kb = k0 + (idx & 3) * 4;
            float4 v = z4;
            if (kb + 3 < KTOT) {
                if (kb + 3 < KIH) v = *(const float4*)&Wih[(size_t)n * KIH + kb];
                else              v = *(const float4*)&Whh[(size_t)n * HH + (kb - KIH)];
            }
            if (i == 0) bR0 = v; else bR1 = v;
        }
    };

    loadP(z * 16);

    for (int panel = z; panel * 16 < KTOT; panel += SPK) {
        sA[(akq * 4 + 0) * 68 + arow] = aR.x; sA[(akq * 4 + 1) * 68 + arow] = aR.y;
        sA[(akq * 4 + 2) * 68 + arow] = aR.z; sA[(akq * 4 + 3) * 68 + arow] = aR.w;
#pragma unroll
        for (int i = 0; i < 2; i++) {
            int idx = t2 + i * 256;
            int nl = idx >> 2, kq = idx & 3;
            float4 v = (i == 0) ? bR0 : bR1;
            sB[(kq * 4 + 0) * 132 + nl] = v.x; sB[(kq * 4 + 1) * 132 + nl] = v.y;
            sB[(kq * 4 + 2) * 132 + nl] = v.z; sB[(kq * 4 + 3) * 132 + nl] = v.w;
        }
        NB(half);

        if ((panel + SPK) * 16 < KTOT) loadP((panel + SPK) * 16);

#pragma unroll
        for (int kk = 0; kk < 16; kk++) {
            float4 a4  = *(const float4*)&sA[kk * 68 + tm * 4];
            float4 b4a = *(const float4*)&sB[kk * 132 + tn * 8];
            float4 b4b = *(const float4*)&sB[kk * 132 + tn * 8 + 4];
            const float ar[4] = {a4.x, a4.y, a4.z, a4.w};
            const float br[8] = {b4a.x, b4a.y, b4a.z, b4a.w, b4b.x, b4b.y, b4b.z, b4b.w};
#pragma unroll
            for (int r = 0; r < 4; r++)
#pragma unroll
                for (int c = 0; c < 8; c++)
                    acc[r][c] = fmaf(ar[r], br[c], acc[r][c]);
        }
        NB(half);
    }

    float* gp = g_gpart[z];
#pragma unroll
    for (int r = 0; r < 4; r++) {
        int row = bm + tm * 4 + r;
        *(float4*)&gp[row * NG + bn + tn * 8] =
            make_float4(acc[r][0], acc[r][1], acc[r][2], acc[r][3]);
        *(float4*)&gp[row * NG + bn + tn * 8 + 4] =
            make_float4(acc[r][4], acc[r][5], acc[r][6], acc[r][7]);
    }
    __threadfence();
    NB(half);
    if (t2 == 0) atomicAdd(&g_gatesdone[t][g], 1u);
}

// --- lstm: combine partials + pointwise (per half), then CTA-COOPERATIVE
// q_{t+1} and out-proj for BOTH batches (weights read once per CTA). ---
__device__ __forceinline__ void lstm_phase(const float* __restrict__ bih,
                                           const float* __restrict__ bhh,
                                           const float* __restrict__ Cdw,
                                           const float* __restrict__ Cdb,
                                           const float* __restrict__ Hcw,
                                           const float* __restrict__ Hcb,
                                           float* __restrict__ out, int t,
                                           int g, unsigned tgt, char* dynsm) {
    const int half = threadIdx.x >> 8;
    const int t2 = threadIdx.x & 255;
    const int b = blockIdx.x * 2 + half;
    float* sh2 = (float*)(dynsm + half * HREG);  // this half's h2 (256 floats)

    wait_ctr(&g_gatesdone[t][g], tgt, half);

    const int base = b * NG;
    float gi = bih[t2]       + bhh[t2];
    float gf = bih[256 + t2] + bhh[256 + t2];
    float gg = bih[512 + t2] + bhh[512 + t2];
    float go = bih[768 + t2] + bhh[768 + t2];
#pragma unroll
    for (int z = 0; z < SPK; z++) {
        const float* gp = g_gpart[z] + base;
        gi += __ldcg(&gp[t2]);
        gf += __ldcg(&gp[256 + t2]);
        gg += __ldcg(&gp[512 + t2]);
        go += __ldcg(&gp[768 + t2]);
    }

    float c2 = sigmoidf_(gf) * g_c[b * HH + t2] + sigmoidf_(gi) * tanhf(gg);
    float h2 = sigmoidf_(go) * tanhf(c2);
    g_c[b * HH + t2] = c2;
    g_inp[b * KTOT + KIH + t2] = h2;       // h for next step
    sh2[t2] = h2;
    __syncthreads();    // BOTH halves: h2 of both batches now in smem

    // ---- cooperative tail: 16 warps, each owns a row-range of Hcw/Cdw and
    // computes for BOTH batches (weights read once per CTA). ----
    const int w = threadIdx.x >> 5, lane = threadIdx.x & 31;
    const float* s0 = (const float*)dynsm;           // batch b0 h2
    const float* s1 = (const float*)(dynsm + HREG);  // batch b1 h2
    const int b0 = blockIdx.x * 2, b1 = b0 + 1;

    float h0[8], h1[8];
#pragma unroll
    for (int i = 0; i < 8; i++) { h0[i] = s0[lane * 8 + i]; h1[i] = s1[lane * 8 + i]; }

    // q_{t+1}: warp w owns j in [w*16, w*16+16)
#pragma unroll 4
    for (int jj = 0; jj < 16; jj++) {
        const int j = w * 16 + jj;
        const float4* r = (const float4*)(Hcw + (size_t)j * HH);
        float4 a = r[lane * 2], bb = r[lane * 2 + 1];
        float s0v = h0[0] * a.x + h0[1] * a.y + h0[2] * a.z + h0[3] * a.w
                  + h0[4] * bb.x + h0[5] * bb.y + h0[6] * bb.z + h0[7] * bb.w;
        float s1v = h1[0] * a.x + h1[1] * a.y + h1[2] * a.z + h1[3] * a.w
                  + h1[4] * bb.x + h1[5] * bb.y + h1[6] * bb.z + h1[7] * bb.w;
        s0v = warp_sum(s0v);
        s1v = warp_sum(s1v);
        if (lane == 0) {
            float bias = Hcb[j];
            g_q[b0 * AA + j] = s0v + bias;
            g_q[b1 * AA + j] = s1v + bias;
        }
    }

    // out-proj: warp w owns v = w + 16k
    for (int v = w; v < VV; v += 16) {
        const float4* r = (const float4*)(Cdw + (size_t)v * HH);
        float4 a = r[lane * 2], bb = r[lane * 2 + 1];
        float s0v = h0[0] * a.x + h0[1] * a.y + h0[2] * a.z + h0[3] * a.w
                  + h0[4] * bb.x + h0[5] * bb.y + h0[6] * bb.z + h0[7] * bb.w;
        float s1v = h1[0] * a.x + h1[1] * a.y + h1[2] * a.z + h1[3] * a.w
                  + h1[4] * bb.x + h1[5] * bb.y + h1[6] * bb.z + h1[7] * bb.w;
        s0v = warp_sum(s0v);
        s1v = warp_sum(s1v);
        if (lane == 0) {
            float bias = Cdb[v];
            float v0 = s0v + bias, v1 = s1v + bias;
            out[((size_t)b0 * TT + t) * VV + v] = v0;
            out[((size_t)b1 * TT + t) * VV + v] = v1;
            g_inp[b0 * KTOT + v] = v0;
            g_inp[b1 * KTOT + v] = v1;
        }
    }

    __threadfence();
    __syncthreads();   // all q/out/h/x fenced; cross-half sh2 reads complete
    if (threadIdx.x == 0 || threadIdx.x == 256) atomicAdd(&g_statedone[t][g], 1u);
}

// ============================================================================
__global__ __launch_bounds__(512, 1) void mega_kernel(
    const float* __restrict__ Hcw, const float* __restrict__ Hcb,
    const float* __restrict__ Wih, const float* __restrict__ Whh,
    const float* __restrict__ bih, const float* __restrict__ bhh,
    const float* __restrict__ Cdw, const float* __restrict__ Cdb,
    float* __restrict__ out) {
    extern __shared__ __align__(16) char dynsm[];
    __shared__ float sm_m[16], sm_s[16];
    __shared__ unsigned s_r;

    if (threadIdx.x == 0) s_r = atomicAdd(&g_round[blockIdx.x], 1u);
    __syncthreads();
    const unsigned tgt = 64u * (s_r + 1u);   // 64 half-signals per group/step
    const int g = blockIdx.x >> 5;           // batch group 0..3

    for (int t = 0; t < TT; t++) {
        attn_phase(dynsm, sm_m, sm_s, t, g, tgt);
        gates_phase(Wih, Whh, dynsm, t, g, tgt);
        lstm_phase(bih, bhh, Cdw, Cdb, Hcw, Hcb, out, t, g, tgt, dynsm);
    }
}

// ============================================================================
extern "C" void kernel_launch(void* const* d_in, const int* in_sizes, int n_in,
                              void* d_out, int out_size) {
    (void)in_sizes; (void)n_in; (void)out_size;
    const float* img  = (const float*)d_in[0];
    const float* tgt  = (const float*)d_in[1];
    const float* Icw  = (const float*)d_in[2];
    const float* Icb  = (const float*)d_in[3];
    const float* Hcw  = (const float*)d_in[4];
    const float* Hcb  = (const float*)d_in[5];
    const float* Wih  = (const float*)d_in[6];
    const float* Whh  = (const float*)d_in[7];
    const float* bih  = (const float*)d_in[8];
    const float* bhh  = (const float*)d_in[9];
    const float* Cdw  = (const float*)d_in[10];
    const float* Cdb  = (const float*)d_in[11];
    float* out = (float*)d_out;

    const int PROJ_SMEM = 30720;  // fp16 tiles
    cudaFuncSetAttribute(proj_kernel, cudaFuncAttributeMaxDynamicSharedMemorySize,
                         PROJ_SMEM);
    const int MEGA_SMEM = 65536;  // 2 x 32 KB half-regions
    cudaFuncSetAttribute(mega_kernel, cudaFuncAttributeMaxDynamicSharedMemorySize,
                         MEGA_SMEM);

    proj_kernel<<<dim3((BB * PP) / 64, AA / 128), 256, PROJ_SMEM>>>(img, Icw, Icb);
    init_kernel<<<BB, 256>>>(tgt, Hcb);
    mega_kernel<<<GRID, 512, MEGA_SMEM>>>(Hcw, Hcb, Wih, Whh, bih, bhh, Cdw, Cdb, out);
}